// round 1
// baseline (speedup 1.0000x reference)
#include <cuda_runtime.h>
#include <mma.h>

using namespace nvcuda;

// Problem constants
#define BB    8
#define NTOK  4096
#define CDIM  768
#define HN    12
#define HDIM  64
#define NWIN  16     // windows per image (4x4)
#define NWTOK 256    // tokens per window (16x16)
#define BWH   (BB*NWIN*HN)   // 1536
#define ASCALE 0.125f

// Scratch: qkv staged as [s][bwh][t][d] ; attention out as [bwh][t][d]
__device__ __align__(128) float g_qkv[3u * 1536u * 256u * 64u];
__device__ __align__(128) float g_att[1536u * 256u * 64u];

// ---------------------------------------------------------------------------
// Kernel 1: fused window-permute + QKV GEMM (TF32 wmma, NT)
//   Y[m, j] = sum_k x[b, perm(m), k] * qkv_w[j, k]
//   m = b*4096 + w*256 + t  (permuted order), j = s*768 + h*64 + d
//   64x64 output tile per block, BK=16, 4 warps each doing 32x32.
// ---------------------------------------------------------------------------
__global__ __launch_bounds__(128) void qkv_gemm(const float* __restrict__ x,
                                                const float* __restrict__ w) {
    __shared__ float As[64][20];
    __shared__ float Bs[64][20];
    __shared__ float Cs[64][64];
    __shared__ const float* Arow[64];

    const int tid = threadIdx.x;
    const int bx = blockIdx.x;   // 0..35  (col tiles over 2304)
    const int by = blockIdx.y;   // 0..511 (row tiles over 32768)

    if (tid < 64) {
        int gm = by * 64 + tid;
        int b = gm >> 12;
        int p = gm & 4095;
        int wdw = p >> 8;        // window 0..15
        int t = p & 255;         // token in window
        int wr = wdw >> 2, wc = wdw & 3, r = t >> 4, c = t & 15;
        int orig = ((wr * 16 + r) << 6) + (wc * 16 + c);
        Arow[tid] = x + (size_t)(b * 4096 + orig) * 768;
    }

    const int warp = tid >> 5;
    const int wr2 = warp >> 1, wc2 = warp & 1;

    wmma::fragment<wmma::accumulator, 16, 16, 8, float> acc[2][2];
#pragma unroll
    for (int i = 0; i < 2; i++)
#pragma unroll
        for (int j = 0; j < 2; j++) wmma::fill_fragment(acc[i][j], 0.0f);

    __syncthreads();

    const int n0 = bx * 64;

    for (int k0 = 0; k0 < 768; k0 += 16) {
#pragma unroll
        for (int rep = 0; rep < 2; rep++) {
            int ii = tid + rep * 128;
            int row = ii >> 2;
            int kq = (ii & 3) << 2;
            *(float4*)&As[row][kq] = *(const float4*)(Arow[row] + k0 + kq);
            *(float4*)&Bs[row][kq] = *(const float4*)(w + (size_t)(n0 + row) * 768 + k0 + kq);
        }
        __syncthreads();

#pragma unroll
        for (int ks = 0; ks < 16; ks += 8) {
            wmma::fragment<wmma::matrix_a, 16, 16, 8, wmma::precision::tf32, wmma::row_major> af[2];
            wmma::fragment<wmma::matrix_b, 16, 16, 8, wmma::precision::tf32, wmma::col_major> bf[2];
#pragma unroll
            for (int i = 0; i < 2; i++) {
                wmma::load_matrix_sync(af[i], &As[wr2 * 32 + i * 16][ks], 20);
#pragma unroll
                for (int e = 0; e < af[i].num_elements; e++)
                    af[i].x[e] = wmma::__float_to_tf32(af[i].x[e]);
            }
#pragma unroll
            for (int j = 0; j < 2; j++) {
                wmma::load_matrix_sync(bf[j], &Bs[wc2 * 32 + j * 16][ks], 20);
#pragma unroll
                for (int e = 0; e < bf[j].num_elements; e++)
                    bf[j].x[e] = wmma::__float_to_tf32(bf[j].x[e]);
            }
#pragma unroll
            for (int i = 0; i < 2; i++)
#pragma unroll
                for (int j = 0; j < 2; j++)
                    wmma::mma_sync(acc[i][j], af[i], bf[j], acc[i][j]);
        }
        __syncthreads();
    }

#pragma unroll
    for (int i = 0; i < 2; i++)
#pragma unroll
        for (int j = 0; j < 2; j++)
            wmma::store_matrix_sync(&Cs[wr2 * 32 + i * 16][wc2 * 32 + j * 16], acc[i][j],
                                    64, wmma::mem_row_major);
    __syncthreads();

    // 64-col tile lies entirely inside one (s, h); 64-row tile inside one (b, w)
    int s = n0 / 768;
    int h = (n0 - s * 768) >> 6;
    int gm0 = by * 64;
    int b = gm0 >> 12;
    int p = gm0 & 4095;
    int wdw = p >> 8;
    int t0 = p & 255;
    float* dst = g_qkv + ((size_t)(s * 1536 + (b * 16 + wdw) * 12 + h) * 256 + t0) * 64;

    for (int i = tid; i < 1024; i += 128) {   // 1024 float4s = 64x64 floats
        int rr = i >> 4;
        int cc = (i & 15) << 2;
        *(float4*)(dst + rr * 64 + cc) = *(float4*)&Cs[rr][cc];
    }
}

// ---------------------------------------------------------------------------
// Kernel 2: windowed attention, one block per (b, window, head).
//   Flash-style: 1 query per thread (256 threads), KV in 32-key smem tiles.
// ---------------------------------------------------------------------------
__global__ __launch_bounds__(256) void attn_kernel() {
    const int bwh = blockIdx.x;
    const int t = threadIdx.x;
    const float* qp = g_qkv + (size_t)bwh * 16384;
    const float* kp = g_qkv + (size_t)(1536 + bwh) * 16384;
    const float* vp = g_qkv + (size_t)(2 * 1536 + bwh) * 16384;

    __shared__ float Ks[32][64];
    __shared__ float Vs[32][64];

    float q[64];
#pragma unroll
    for (int d4 = 0; d4 < 16; d4++) {
        float4 v = *(const float4*)(qp + t * 64 + d4 * 4);
        q[d4 * 4 + 0] = v.x; q[d4 * 4 + 1] = v.y;
        q[d4 * 4 + 2] = v.z; q[d4 * 4 + 3] = v.w;
    }

    float o[64];
#pragma unroll
    for (int d = 0; d < 64; d++) o[d] = 0.0f;
    float m = -1e30f, l = 0.0f;

    for (int kt = 0; kt < 8; kt++) {
        int base = kt * 32 * 64;
#pragma unroll
        for (int i = t; i < 512; i += 256) {   // 512 float4 per tile
            ((float4*)&Ks[0][0])[i] = ((const float4*)(kp + base))[i];
            ((float4*)&Vs[0][0])[i] = ((const float4*)(vp + base))[i];
        }
        __syncthreads();

        float sbuf[32];
        float tmax = -1e30f;
#pragma unroll 2
        for (int j = 0; j < 32; j++) {
            float a0 = 0.f, a1 = 0.f, a2 = 0.f, a3 = 0.f;
#pragma unroll
            for (int d = 0; d < 64; d += 4) {
                a0 += q[d + 0] * Ks[j][d + 0];
                a1 += q[d + 1] * Ks[j][d + 1];
                a2 += q[d + 2] * Ks[j][d + 2];
                a3 += q[d + 3] * Ks[j][d + 3];
            }
            float sc = ((a0 + a1) + (a2 + a3)) * ASCALE;
            sbuf[j] = sc;
            tmax = fmaxf(tmax, sc);
        }

        float newm = fmaxf(m, tmax);
        float corr = __expf(m - newm);
        l *= corr;
#pragma unroll
        for (int d = 0; d < 64; d++) o[d] *= corr;

#pragma unroll 2
        for (int j = 0; j < 32; j++) {
            float pj = __expf(sbuf[j] - newm);
            l += pj;
#pragma unroll
            for (int d = 0; d < 64; d++) o[d] += pj * Vs[j][d];
        }
        m = newm;
        __syncthreads();
    }

    float inv = 1.0f / l;
    float* op = g_att + (size_t)bwh * 16384 + t * 64;
#pragma unroll
    for (int d4 = 0; d4 < 16; d4++) {
        float4 v;
        v.x = o[d4 * 4 + 0] * inv; v.y = o[d4 * 4 + 1] * inv;
        v.z = o[d4 * 4 + 2] * inv; v.w = o[d4 * 4 + 3] * inv;
        *(float4*)(op + d4 * 4) = v;
    }
}

// ---------------------------------------------------------------------------
// Kernel 3: fused inverse-permute + head-merge + proj GEMM (TF32 wmma, NT) + bias
//   out[b*4096+n, c] = sum_k g_att[(b,w,h=k/64)][t][k%64] * proj_w[c, k] + proj_b[c]
//   (w, t) derived from original token index n via inverse window perm.
// ---------------------------------------------------------------------------
__global__ __launch_bounds__(128) void proj_gemm(const float* __restrict__ w,
                                                 const float* __restrict__ bias,
                                                 float* __restrict__ out) {
    __shared__ float As[64][20];
    __shared__ float Bs[64][20];
    __shared__ float Cs[64][64];
    __shared__ const float* Abase[64];

    const int tid = threadIdx.x;
    const int bx = blockIdx.x;   // 0..11  (col tiles over 768)
    const int by = blockIdx.y;   // 0..511

    if (tid < 64) {
        int gm = by * 64 + tid;
        int b = gm >> 12;
        int n = gm & 4095;
        int row = n >> 6, col = n & 63;
        int wr = row >> 4, r = row & 15, wc = col >> 4, c = col & 15;
        int wdw = wr * 4 + wc;
        int t = r * 16 + c;
        Abase[tid] = g_att + ((size_t)(b * 16 + wdw) * 12 * 256 + t) * 64;
    }

    const int warp = tid >> 5;
    const int wr2 = warp >> 1, wc2 = warp & 1;

    wmma::fragment<wmma::accumulator, 16, 16, 8, float> acc[2][2];
#pragma unroll
    for (int i = 0; i < 2; i++)
#pragma unroll
        for (int j = 0; j < 2; j++) wmma::fill_fragment(acc[i][j], 0.0f);

    __syncthreads();

    const int n0 = bx * 64;

    for (int k0 = 0; k0 < 768; k0 += 16) {
#pragma unroll
        for (int rep = 0; rep < 2; rep++) {
            int ii = tid + rep * 128;
            int row = ii >> 2;
            int kq = (ii & 3) << 2;
            int k = k0 + kq;
            const float* src = Abase[row] + (k >> 6) * 16384 + (k & 63);
            *(float4*)&As[row][kq] = *(const float4*)src;
            *(float4*)&Bs[row][kq] = *(const float4*)(w + (size_t)(n0 + row) * 768 + k0 + kq);
        }
        __syncthreads();

#pragma unroll
        for (int ks = 0; ks < 16; ks += 8) {
            wmma::fragment<wmma::matrix_a, 16, 16, 8, wmma::precision::tf32, wmma::row_major> af[2];
            wmma::fragment<wmma::matrix_b, 16, 16, 8, wmma::precision::tf32, wmma::col_major> bf[2];
#pragma unroll
            for (int i = 0; i < 2; i++) {
                wmma::load_matrix_sync(af[i], &As[wr2 * 32 + i * 16][ks], 20);
#pragma unroll
                for (int e = 0; e < af[i].num_elements; e++)
                    af[i].x[e] = wmma::__float_to_tf32(af[i].x[e]);
            }
#pragma unroll
            for (int j = 0; j < 2; j++) {
                wmma::load_matrix_sync(bf[j], &Bs[wc2 * 32 + j * 16][ks], 20);
#pragma unroll
                for (int e = 0; e < bf[j].num_elements; e++)
                    bf[j].x[e] = wmma::__float_to_tf32(bf[j].x[e]);
            }
#pragma unroll
            for (int i = 0; i < 2; i++)
#pragma unroll
                for (int j = 0; j < 2; j++)
                    wmma::mma_sync(acc[i][j], af[i], bf[j], acc[i][j]);
        }
        __syncthreads();
    }

#pragma unroll
    for (int i = 0; i < 2; i++)
#pragma unroll
        for (int j = 0; j < 2; j++)
            wmma::store_matrix_sync(&Cs[wr2 * 32 + i * 16][wc2 * 32 + j * 16], acc[i][j],
                                    64, wmma::mem_row_major);
    __syncthreads();

    float* dst = out + (size_t)(by * 64) * 768 + n0;
    for (int i = tid; i < 1024; i += 128) {
        int rr = i >> 4;
        int cc = (i & 15) << 2;
        float4 v = *(float4*)&Cs[rr][cc];
        v.x += bias[n0 + cc + 0];
        v.y += bias[n0 + cc + 1];
        v.z += bias[n0 + cc + 2];
        v.w += bias[n0 + cc + 3];
        *(float4*)(dst + (size_t)rr * 768 + cc) = v;
    }
}

// ---------------------------------------------------------------------------
extern "C" void kernel_launch(void* const* d_in, const int* in_sizes, int n_in,
                              void* d_out, int out_size) {
    const float* x      = (const float*)d_in[0];
    const float* qkv_w  = (const float*)d_in[1];
    const float* proj_w = (const float*)d_in[2];
    const float* proj_b = (const float*)d_in[3];
    float* out = (float*)d_out;

    dim3 g1(36, 512);
    qkv_gemm<<<g1, 128>>>(x, qkv_w);

    attn_kernel<<<1536, 256>>>();

    dim3 g2(12, 512);
    proj_gemm<<<g2, 128>>>(proj_w, proj_b, out);
}